// round 1
// baseline (speedup 1.0000x reference)
#include <cuda_runtime.h>
#include <math.h>

// ---------------- problem constants ----------------
constexpr int B_  = 32;
constexpr int S_  = 576;
constexpr int E_  = 768;
constexpr int H_  = 12;
constexpr int D_  = 64;
constexpr int BS_ = B_ * S_;                    // 18432
constexpr long OUT1  = (long)BS_ * E_;          // 14,155,776
constexpr long NATTN = (long)B_ * H_ * S_ * S_; // 127,401,984
constexpr float SCALE_ = 0.125f;                // 64^-0.5

// ---------------- device scratch (no cudaMalloc allowed) ----------------
__device__ float g_q[BS_ * E_];
__device__ float g_k[BS_ * E_];
__device__ float g_v[BS_ * E_];
__device__ float g_ctx[BS_ * E_];
__device__ float g_attn[(size_t)B_ * H_ * S_ * S_];  // fallback if attn not in d_out

// ============================================================================
// Generic tiled GEMM:  C = alpha * A[M,K] * B[N,K]^T (+ bias[n])
// 64x64 tile, BK=16, 256 threads, 4x4 per thread. All dims multiples of tile.
// layout==0: C[m*N+n] (plain row-major, ldc=N)
// layout==1: QKV epilogue -> [B,H,S,D]:  m=b*S+s, n=h*D+d
// Batched via blockIdx.z with strides sA/sB/sC.
// ============================================================================
__global__ void gemm_nt_kernel(const float* __restrict__ A,
                               const float* __restrict__ Bw,
                               const float* __restrict__ bias,
                               float* __restrict__ C,
                               int M, int N, int K,
                               long sA, long sB, long sC,
                               float alpha, int layout)
{
    A  += (long)blockIdx.z * sA;
    Bw += (long)blockIdx.z * sB;
    C  += (long)blockIdx.z * sC;

    __shared__ float As[16][68];
    __shared__ float Bs[16][68];

    const int tid = threadIdx.x;
    const int bm  = blockIdx.y * 64;
    const int bn  = blockIdx.x * 64;
    const int tr  = (tid >> 4) << 2;   // row base within tile
    const int tc  = (tid & 15) << 2;   // col base within tile
    const int lr  = tid >> 2;          // load row 0..63
    const int lk  = (tid & 3) << 2;    // load k offset 0,4,8,12

    float acc[4][4] = {};

    for (int k0 = 0; k0 < K; k0 += 16) {
        float4 av = *reinterpret_cast<const float4*>(A  + (long)(bm + lr) * K + k0 + lk);
        As[lk + 0][lr] = av.x; As[lk + 1][lr] = av.y;
        As[lk + 2][lr] = av.z; As[lk + 3][lr] = av.w;
        float4 bv = *reinterpret_cast<const float4*>(Bw + (long)(bn + lr) * K + k0 + lk);
        Bs[lk + 0][lr] = bv.x; Bs[lk + 1][lr] = bv.y;
        Bs[lk + 2][lr] = bv.z; Bs[lk + 3][lr] = bv.w;
        __syncthreads();

        #pragma unroll
        for (int k = 0; k < 16; k++) {
            float a0 = As[k][tr + 0], a1 = As[k][tr + 1];
            float a2 = As[k][tr + 2], a3 = As[k][tr + 3];
            float b0 = Bs[k][tc + 0], b1 = Bs[k][tc + 1];
            float b2 = Bs[k][tc + 2], b3 = Bs[k][tc + 3];
            acc[0][0] += a0 * b0; acc[0][1] += a0 * b1; acc[0][2] += a0 * b2; acc[0][3] += a0 * b3;
            acc[1][0] += a1 * b0; acc[1][1] += a1 * b1; acc[1][2] += a1 * b2; acc[1][3] += a1 * b3;
            acc[2][0] += a2 * b0; acc[2][1] += a2 * b1; acc[2][2] += a2 * b2; acc[2][3] += a2 * b3;
            acc[3][0] += a3 * b0; acc[3][1] += a3 * b1; acc[3][2] += a3 * b2; acc[3][3] += a3 * b3;
        }
        __syncthreads();
    }

    #pragma unroll
    for (int i = 0; i < 4; i++) {
        const int m = bm + tr + i;
        #pragma unroll
        for (int j = 0; j < 4; j++) {
            const int n = bn + tc + j;
            float v = acc[i][j] * alpha;
            if (bias) v += bias[n];
            if (layout == 0) {
                C[(long)m * N + n] = v;
            } else {
                // [B,H,S,D]: b = m/S, s = m%S, h = n/D, d = n%D
                long idx = (long)(m / S_) * (H_ * S_ * D_)
                         + (long)(n / D_) * (S_ * D_)
                         + (long)(m % S_) * D_
                         + (n % D_);
                C[idx] = v;
            }
        }
    }
}

// ============================================================================
// PV GEMM (NN): ctx[s, h*D+d] = sum_j attn[bh][s,j] * V[bh][j,d]
// per-batch M=576, N=64, K=576. Output written directly into [B,S,E] layout.
// ============================================================================
__global__ void gemm_nn_pv_kernel(const float* __restrict__ attn,
                                  const float* __restrict__ V,
                                  float* __restrict__ ctx)
{
    const int bh = blockIdx.z;
    const float* A  = attn + (long)bh * S_ * S_;
    const float* Bv = V    + (long)bh * S_ * D_;
    float* C = ctx + (long)(bh / H_) * S_ * E_ + (long)(bh % H_) * D_;

    __shared__ float As[16][68];
    __shared__ float Bs[16][68];

    const int tid = threadIdx.x;
    const int bm  = blockIdx.y * 64;
    const int tr  = (tid >> 4) << 2;
    const int tc  = (tid & 15) << 2;
    const int lr  = tid >> 2;          // A load row 0..63
    const int lk  = (tid & 3) << 2;    // A load k offset
    const int bk  = tid >> 4;          // B load row (k) 0..15
    const int bn4 = (tid & 15) << 2;   // B load col 0..60

    float acc[4][4] = {};

    for (int k0 = 0; k0 < S_; k0 += 16) {
        float4 av = *reinterpret_cast<const float4*>(A + (long)(bm + lr) * S_ + k0 + lk);
        As[lk + 0][lr] = av.x; As[lk + 1][lr] = av.y;
        As[lk + 2][lr] = av.z; As[lk + 3][lr] = av.w;
        float4 bv = *reinterpret_cast<const float4*>(Bv + (long)(k0 + bk) * D_ + bn4);
        Bs[bk][bn4 + 0] = bv.x; Bs[bk][bn4 + 1] = bv.y;
        Bs[bk][bn4 + 2] = bv.z; Bs[bk][bn4 + 3] = bv.w;
        __syncthreads();

        #pragma unroll
        for (int k = 0; k < 16; k++) {
            float a0 = As[k][tr + 0], a1 = As[k][tr + 1];
            float a2 = As[k][tr + 2], a3 = As[k][tr + 3];
            float b0 = Bs[k][tc + 0], b1 = Bs[k][tc + 1];
            float b2 = Bs[k][tc + 2], b3 = Bs[k][tc + 3];
            acc[0][0] += a0 * b0; acc[0][1] += a0 * b1; acc[0][2] += a0 * b2; acc[0][3] += a0 * b3;
            acc[1][0] += a1 * b0; acc[1][1] += a1 * b1; acc[1][2] += a1 * b2; acc[1][3] += a1 * b3;
            acc[2][0] += a2 * b0; acc[2][1] += a2 * b1; acc[2][2] += a2 * b2; acc[2][3] += a2 * b3;
            acc[3][0] += a3 * b0; acc[3][1] += a3 * b1; acc[3][2] += a3 * b2; acc[3][3] += a3 * b3;
        }
        __syncthreads();
    }

    #pragma unroll
    for (int i = 0; i < 4; i++)
        #pragma unroll
        for (int j = 0; j < 4; j++)
            C[(long)(bm + tr + i) * E_ + tc + j] = acc[i][j];
}

// ============================================================================
// Row softmax in place: one block (128 thr) per row of 576.
// ============================================================================
__global__ void softmax_kernel(float* __restrict__ attn)
{
    float* p = attn + (long)blockIdx.x * S_;
    const int tid = threadIdx.x;

    float vals[5];
    float m = -INFINITY;
    #pragma unroll
    for (int j = 0; j < 5; j++) {
        int i = tid + j * 128;
        vals[j] = (i < S_) ? p[i] : -INFINITY;
        m = fmaxf(m, vals[j]);
    }
    #pragma unroll
    for (int o = 16; o; o >>= 1) m = fmaxf(m, __shfl_xor_sync(0xffffffffu, m, o));
    __shared__ float smax[4];
    __shared__ float ssum[4];
    if ((tid & 31) == 0) smax[tid >> 5] = m;
    __syncthreads();
    m = fmaxf(fmaxf(smax[0], smax[1]), fmaxf(smax[2], smax[3]));

    float s = 0.f;
    #pragma unroll
    for (int j = 0; j < 5; j++) {
        int i = tid + j * 128;
        vals[j] = (i < S_) ? expf(vals[j] - m) : 0.f;
        s += vals[j];
    }
    #pragma unroll
    for (int o = 16; o; o >>= 1) s += __shfl_xor_sync(0xffffffffu, s, o);
    if ((tid & 31) == 0) ssum[tid >> 5] = s;
    __syncthreads();
    s = ssum[0] + ssum[1] + ssum[2] + ssum[3];
    const float inv = 1.f / s;

    #pragma unroll
    for (int j = 0; j < 5; j++) {
        int i = tid + j * 128;
        if (i < S_) p[i] = vals[j] * inv;
    }
}

// ============================================================================
// Launch
// ============================================================================
extern "C" void kernel_launch(void* const* d_in, const int* in_sizes, int n_in,
                              void* d_out, int out_size)
{
    const float* hs = (const float*)d_in[0];
    const float* qw = (const float*)d_in[1];
    const float* qb = (const float*)d_in[2];
    const float* kw = (const float*)d_in[3];
    const float* kb = (const float*)d_in[4];
    const float* vw = (const float*)d_in[5];
    const float* vb = (const float*)d_in[6];
    const float* ow = (const float*)d_in[7];
    const float* ob = (const float*)d_in[8];
    float* out = (float*)d_out;

    float *pq, *pk, *pv, *pctx, *pattn_fb;
    cudaGetSymbolAddress((void**)&pq,       g_q);
    cudaGetSymbolAddress((void**)&pk,       g_k);
    cudaGetSymbolAddress((void**)&pv,       g_v);
    cudaGetSymbolAddress((void**)&pctx,     g_ctx);
    cudaGetSymbolAddress((void**)&pattn_fb, g_attn);

    float* attn = ((long)out_size >= OUT1 + NATTN) ? (out + OUT1) : pattn_fb;

    const dim3 blk(256);

    // 1. QKV projections -> [B,H,S,D] scratch
    dim3 gproj(E_ / 64, BS_ / 64, 1);
    gemm_nt_kernel<<<gproj, blk>>>(hs, qw, qb, pq, BS_, E_, E_, 0, 0, 0, 1.f, 1);
    gemm_nt_kernel<<<gproj, blk>>>(hs, kw, kb, pk, BS_, E_, E_, 0, 0, 0, 1.f, 1);
    gemm_nt_kernel<<<gproj, blk>>>(hs, vw, vb, pv, BS_, E_, E_, 0, 0, 0, 1.f, 1);

    // 2. Scores = scale * Q K^T  (batched over B*H), written into attn buffer
    dim3 gsc(S_ / 64, S_ / 64, B_ * H_);
    gemm_nt_kernel<<<gsc, blk>>>(pq, pk, nullptr, attn, S_, S_, D_,
                                 (long)S_ * D_, (long)S_ * D_, (long)S_ * S_,
                                 SCALE_, 0);

    // 3. Softmax in place (this is also the attn output)
    softmax_kernel<<<B_ * H_ * S_, 128>>>(attn);

    // 4. PV -> ctx in [B,S,E] layout
    dim3 gpv(1, S_ / 64, B_ * H_);
    gemm_nn_pv_kernel<<<gpv, blk>>>(attn, pv, pctx);

    // 5. Output projection -> first OUT1 elements of d_out
    gemm_nt_kernel<<<gproj, blk>>>(pctx, ow, ob, out, BS_, E_, E_, 0, 0, 0, 1.f, 0);
}

// round 3
// speedup vs baseline: 2.3167x; 2.3167x over previous
#include <cuda_runtime.h>
#include <cuda_bf16.h>
#include <math.h>
#include <stdint.h>

// ---------------- problem constants ----------------
constexpr int B_  = 32;
constexpr int S_  = 576;
constexpr int E_  = 768;
constexpr int H_  = 12;
constexpr int D_  = 64;
constexpr int BS_ = B_ * S_;                    // 18432
constexpr long OUT1  = (long)BS_ * E_;          // 14,155,776
constexpr long NATTN = (long)B_ * H_ * S_ * S_; // 127,401,984
constexpr float SCALE_ = 0.125f;

// ---------------- device scratch ----------------
__device__ unsigned g_hs_pk [BS_ * E_];
__device__ unsigned g_qw_pk [E_ * E_];
__device__ unsigned g_kw_pk [E_ * E_];
__device__ unsigned g_vw_pk [E_ * E_];
__device__ unsigned g_ow_pk [E_ * E_];
__device__ unsigned g_q_pk  [BS_ * E_];   // [B,H,S,D] packed (hi|lo<<16)
__device__ unsigned g_k_pk  [BS_ * E_];   // [B,H,S,D]
__device__ unsigned g_v_pk  [BS_ * E_];   // [B,H,D,S]  (transposed)
__device__ unsigned g_ctx_pk[BS_ * E_];   // [B*S, E]
__device__ float    g_attn  [(size_t)NATTN];

// ---------------- helpers ----------------
__device__ __forceinline__ uint32_t smem_u32(const void* p) {
    uint32_t a;
    asm("{ .reg .u64 t; cvta.to.shared.u64 t, %1; cvt.u32.u64 %0, t; }" : "=r"(a) : "l"(p));
    return a;
}
__device__ __forceinline__ unsigned pack2u(__nv_bfloat16 a, __nv_bfloat16 b) {
    return (unsigned)__bfloat16_as_ushort(a) | ((unsigned)__bfloat16_as_ushort(b) << 16);
}
__device__ __forceinline__ unsigned packf(float x) {
    __nv_bfloat16 h = __float2bfloat16(x);
    __nv_bfloat16 l = __float2bfloat16(x - __bfloat162float(h));
    return pack2u(h, l);
}
__device__ __forceinline__ void ldsm4(unsigned* r, uint32_t addr) {
    asm volatile("ldmatrix.sync.aligned.m8n8.x4.shared.b16 {%0,%1,%2,%3}, [%4];"
                 : "=r"(r[0]), "=r"(r[1]), "=r"(r[2]), "=r"(r[3]) : "r"(addr));
}
__device__ __forceinline__ void mma16816(float* d, const unsigned* a, const unsigned* b) {
    asm volatile(
        "mma.sync.aligned.m16n8k16.row.col.f32.bf16.bf16.f32 "
        "{%0,%1,%2,%3}, {%4,%5,%6,%7}, {%8,%9}, {%0,%1,%2,%3};"
        : "+f"(d[0]), "+f"(d[1]), "+f"(d[2]), "+f"(d[3])
        : "r"(a[0]), "r"(a[1]), "r"(a[2]), "r"(a[3]), "r"(b[0]), "r"(b[1]));
}

// ---------------- pack fp32 -> (bf16 hi | bf16 lo<<16) ----------------
__global__ void pack_split_kernel(const float* __restrict__ src,
                                  unsigned* __restrict__ dst, long n) {
    for (long i = (long)blockIdx.x * blockDim.x + threadIdx.x; i < n;
         i += (long)gridDim.x * blockDim.x)
        dst[i] = packf(src[i]);
}

// ============================================================================
// HMMA bf16-split GEMM:  D[m,n] = scale * sum_k A[m,k]*B[n,k] (+ bias[n])
// Block tile 128x64, 8 warps (warp tile 32x32), BK=32, double-buffered SMEM.
// 3 tensor passes: AhBh + AhBl + AlBh  (fp32-grade accuracy).
// AMODE: 0 = A is packed unsigned (hi|lo), 1 = A is fp32 (split on the fly)
// MODE:  0 out fp32+bias [M,E]       1 q/k packed -> [B,H,S,D] (+bias)
//        2 v packed -> [B,H,D,S] (+bias)   3 scores fp32*scale -> [z,S,S]
//        4 ctx packed -> [B*S, E]
// ============================================================================
constexpr int LDS_  = 40;               // bf16 elems per smem row (80B, conflict-free)
constexpr int A_H_  = 0;                // elem offsets within a stage
constexpr int A_L_  = 128 * LDS_;       // 5120
constexpr int B_H_  = 256 * LDS_;       // 10240
constexpr int B_L_  = B_H_ + 64 * LDS_; // 12800
constexpr int STG_E = B_L_ + 64 * LDS_; // 15360 elems
constexpr int STG_B = STG_E * 2;        // 30720 bytes
constexpr int SMEMSZ = 2 * STG_B;       // 61440

template<int AMODE, int MODE>
__global__ void __launch_bounds__(256)
hgemm(const void* __restrict__ Aptr, const unsigned* __restrict__ Bptr,
      const float* __restrict__ bias, void* __restrict__ Cptr,
      int lda, int ldb, long sA, long sB, int NC, int Mclamp, float scale)
{
    extern __shared__ char smem[];
    __nv_bfloat16* sm = (__nv_bfloat16*)smem;
    const uint32_t sbase = smem_u32(smem);

    const int tid = threadIdx.x, lane = tid & 31, wid = tid >> 5;
    const int warp_m = wid >> 1, warp_n = wid & 1;
    const int bm = blockIdx.y * 128, bn = blockIdx.x * 64, z = blockIdx.z;

    const unsigned* Ap = (const unsigned*)Aptr + (long)z * sA;
    const float*    Af = (const float*)Aptr + (long)z * sA;
    const unsigned* Bp = Bptr + (long)z * sB;

    const int ar = tid >> 4;          // 0..15
    const int ac = (tid & 15) * 2;    // 0..30

    float acc[2][4][4];
    #pragma unroll
    for (int i = 0; i < 2; i++)
        #pragma unroll
        for (int j = 0; j < 4; j++)
            #pragma unroll
            for (int r = 0; r < 4; r++) acc[i][j][r] = 0.f;

    uint2  pa[8];
    float2 fa[8];
    uint2  pb[4];

    auto loadA = [&](int k0) {
        #pragma unroll
        for (int i = 0; i < 8; i++) {
            const int gr = bm + ar + 16 * i;
            if (AMODE == 0)
                pa[i] = (gr < Mclamp) ? *(const uint2*)(Ap + (long)gr * lda + k0 + ac)
                                      : make_uint2(0u, 0u);
            else
                fa[i] = (gr < Mclamp) ? *(const float2*)(Af + (long)gr * lda + k0 + ac)
                                      : make_float2(0.f, 0.f);
        }
        #pragma unroll
        for (int i = 0; i < 4; i++) {
            const int gr = bn + ar + 16 * i;
            pb[i] = *(const uint2*)(Bp + (long)gr * ldb + k0 + ac);
        }
    };

    auto stage = [&](int buf) {
        __nv_bfloat16* s = sm + buf * STG_E;
        #pragma unroll
        for (int i = 0; i < 8; i++) {
            const int off = (ar + 16 * i) * LDS_ + ac;
            unsigned hi, lo;
            if (AMODE == 0) {
                hi = __byte_perm(pa[i].x, pa[i].y, 0x5410);
                lo = __byte_perm(pa[i].x, pa[i].y, 0x7632);
            } else {
                __nv_bfloat16 h0 = __float2bfloat16(fa[i].x);
                __nv_bfloat16 h1 = __float2bfloat16(fa[i].y);
                __nv_bfloat16 l0 = __float2bfloat16(fa[i].x - __bfloat162float(h0));
                __nv_bfloat16 l1 = __float2bfloat16(fa[i].y - __bfloat162float(h1));
                hi = pack2u(h0, h1); lo = pack2u(l0, l1);
            }
            *(unsigned*)(s + A_H_ + off) = hi;
            *(unsigned*)(s + A_L_ + off) = lo;
        }
        #pragma unroll
        for (int i = 0; i < 4; i++) {
            const int off = (ar + 16 * i) * LDS_ + ac;
            *(unsigned*)(s + B_H_ + off) = __byte_perm(pb[i].x, pb[i].y, 0x5410);
            *(unsigned*)(s + B_L_ + off) = __byte_perm(pb[i].x, pb[i].y, 0x7632);
        }
    };

    auto compute = [&](int buf) {
        const uint32_t base = sbase + buf * STG_B;
        #pragma unroll
        for (int ks = 0; ks < 2; ks++) {
            unsigned ah[2][4], al[2][4], bh[2][4], bl[2][4];
            #pragma unroll
            for (int mi = 0; mi < 2; mi++) {
                const uint32_t aoff =
                    ((warp_m * 32 + mi * 16 + (lane & 15)) * LDS_ + ks * 16 + ((lane >> 4) << 3)) * 2;
                ldsm4(ah[mi], base + A_H_ * 2 + aoff);
                ldsm4(al[mi], base + A_L_ * 2 + aoff);
            }
            #pragma unroll
            for (int np = 0; np < 2; np++) {
                const uint32_t boff =
                    ((warp_n * 32 + np * 16 + ((lane >> 4) & 1) * 8 + (lane & 7)) * LDS_
                     + ks * 16 + ((lane >> 3) & 1) * 8) * 2;
                ldsm4(bh[np], base + B_H_ * 2 + boff);
                ldsm4(bl[np], base + B_L_ * 2 + boff);
            }
            #pragma unroll
            for (int mi = 0; mi < 2; mi++)
                #pragma unroll
                for (int ni = 0; ni < 4; ni++) {
                    const unsigned* bhf = &bh[ni >> 1][(ni & 1) * 2];
                    const unsigned* blf = &bl[ni >> 1][(ni & 1) * 2];
                    mma16816(acc[mi][ni], ah[mi], bhf);
                    mma16816(acc[mi][ni], ah[mi], blf);
                    mma16816(acc[mi][ni], al[mi], bhf);
                }
        }
    };

    loadA(0);
    for (int c = 0; c < NC; c++) {
        const int buf = c & 1;
        stage(buf);
        __syncthreads();
        if (c + 1 < NC) loadA((c + 1) * 32);
        compute(buf);
        __syncthreads();
    }

    // ---- epilogue ----
    #pragma unroll
    for (int mi = 0; mi < 2; mi++)
        #pragma unroll
        for (int ni = 0; ni < 4; ni++) {
            const int gc = bn + warp_n * 32 + ni * 8 + (lane & 3) * 2;
            float b0 = 0.f, b1 = 0.f;
            if (MODE == 0 || MODE == 1 || MODE == 2) { b0 = bias[gc]; b1 = bias[gc + 1]; }
            #pragma unroll
            for (int r = 0; r < 2; r++) {
                const int gm = bm + warp_m * 32 + mi * 16 + (lane >> 2) + r * 8;
                if (gm >= Mclamp) continue;
                const float v0 = acc[mi][ni][r * 2 + 0] * scale + b0;
                const float v1 = acc[mi][ni][r * 2 + 1] * scale + b1;
                if (MODE == 0) {
                    *(float2*)((float*)Cptr + (long)gm * E_ + gc) = make_float2(v0, v1);
                } else if (MODE == 1) {
                    const int b = gm / S_, s = gm % S_, h = gc >> 6, d = gc & 63;
                    *(uint2*)((unsigned*)Cptr + (((long)b * H_ + h) * S_ + s) * D_ + d)
                        = make_uint2(packf(v0), packf(v1));
                } else if (MODE == 2) {
                    const int b = gm / S_, s = gm % S_, h = gc >> 6, d = gc & 63;
                    unsigned* dst = (unsigned*)Cptr + (((long)b * H_ + h) * D_ + d) * S_ + s;
                    dst[0]  = packf(v0);
                    dst[S_] = packf(v1);
                } else if (MODE == 3) {
                    *(float2*)((float*)Cptr + (long)z * S_ * S_ + (long)gm * S_ + gc)
                        = make_float2(v0, v1);
                } else { // MODE == 4
                    const int b = z / H_, h = z % H_;
                    *(uint2*)((unsigned*)Cptr + ((long)(b * S_ + gm)) * E_ + h * D_ + gc)
                        = make_uint2(packf(v0), packf(v1));
                }
            }
        }
}

// ============================================================================
// Row softmax in place (row length 576)
// ============================================================================
__global__ void softmax_kernel(float* __restrict__ attn)
{
    float* p = attn + (long)blockIdx.x * S_;
    const int tid = threadIdx.x;
    float vals[5];
    float m = -INFINITY;
    #pragma unroll
    for (int j = 0; j < 5; j++) {
        int i = tid + j * 128;
        vals[j] = (i < S_) ? p[i] : -INFINITY;
        m = fmaxf(m, vals[j]);
    }
    #pragma unroll
    for (int o = 16; o; o >>= 1) m = fmaxf(m, __shfl_xor_sync(0xffffffffu, m, o));
    __shared__ float smax[4], ssum[4];
    if ((tid & 31) == 0) smax[tid >> 5] = m;
    __syncthreads();
    m = fmaxf(fmaxf(smax[0], smax[1]), fmaxf(smax[2], smax[3]));
    float s = 0.f;
    #pragma unroll
    for (int j = 0; j < 5; j++) {
        int i = tid + j * 128;
        vals[j] = (i < S_) ? expf(vals[j] - m) : 0.f;
        s += vals[j];
    }
    #pragma unroll
    for (int o = 16; o; o >>= 1) s += __shfl_xor_sync(0xffffffffu, s, o);
    if ((tid & 31) == 0) ssum[tid >> 5] = s;
    __syncthreads();
    s = ssum[0] + ssum[1] + ssum[2] + ssum[3];
    const float inv = 1.f / s;
    #pragma unroll
    for (int j = 0; j < 5; j++) {
        int i = tid + j * 128;
        if (i < S_) p[i] = vals[j] * inv;
    }
}

// ============================================================================
// Launch
// ============================================================================
extern "C" void kernel_launch(void* const* d_in, const int* in_sizes, int n_in,
                              void* d_out, int out_size)
{
    const float* hs = (const float*)d_in[0];
    const float* qw = (const float*)d_in[1];
    const float* qb = (const float*)d_in[2];
    const float* kw = (const float*)d_in[3];
    const float* kb = (const float*)d_in[4];
    const float* vw = (const float*)d_in[5];
    const float* vb = (const float*)d_in[6];
    const float* ow = (const float*)d_in[7];
    const float* ob = (const float*)d_in[8];
    float* out = (float*)d_out;

    unsigned *hs_pk, *qw_pk, *kw_pk, *vw_pk, *ow_pk, *q_pk, *k_pk, *v_pk, *ctx_pk;
    float* attn_fb;
    cudaGetSymbolAddress((void**)&hs_pk, g_hs_pk);
    cudaGetSymbolAddress((void**)&qw_pk, g_qw_pk);
    cudaGetSymbolAddress((void**)&kw_pk, g_kw_pk);
    cudaGetSymbolAddress((void**)&vw_pk, g_vw_pk);
    cudaGetSymbolAddress((void**)&ow_pk, g_ow_pk);
    cudaGetSymbolAddress((void**)&q_pk,  g_q_pk);
    cudaGetSymbolAddress((void**)&k_pk,  g_k_pk);
    cudaGetSymbolAddress((void**)&v_pk,  g_v_pk);
    cudaGetSymbolAddress((void**)&ctx_pk, g_ctx_pk);
    cudaGetSymbolAddress((void**)&attn_fb, g_attn);
    float* attn = ((long)out_size >= OUT1 + NATTN) ? (out + OUT1) : attn_fb;

    cudaFuncSetAttribute(hgemm<0,0>, cudaFuncAttributeMaxDynamicSharedMemorySize, SMEMSZ);
    cudaFuncSetAttribute(hgemm<0,1>, cudaFuncAttributeMaxDynamicSharedMemorySize, SMEMSZ);
    cudaFuncSetAttribute(hgemm<0,2>, cudaFuncAttributeMaxDynamicSharedMemorySize, SMEMSZ);
    cudaFuncSetAttribute(hgemm<0,3>, cudaFuncAttributeMaxDynamicSharedMemorySize, SMEMSZ);
    cudaFuncSetAttribute(hgemm<1,4>, cudaFuncAttributeMaxDynamicSharedMemorySize, SMEMSZ);

    // 0. pack inputs
    pack_split_kernel<<<2048, 256>>>(hs, hs_pk, (long)BS_ * E_);
    pack_split_kernel<<<512, 256>>>(qw, qw_pk, (long)E_ * E_);
    pack_split_kernel<<<512, 256>>>(kw, kw_pk, (long)E_ * E_);
    pack_split_kernel<<<512, 256>>>(vw, vw_pk, (long)E_ * E_);
    pack_split_kernel<<<512, 256>>>(ow, ow_pk, (long)E_ * E_);

    // 1. QKV projections (M=18432, N=768, K=768)
    dim3 gproj(E_ / 64, BS_ / 128, 1);
    hgemm<0,1><<<gproj, 256, SMEMSZ>>>(hs_pk, qw_pk, qb, q_pk, E_, E_, 0, 0, 24, BS_, 1.f);
    hgemm<0,1><<<gproj, 256, SMEMSZ>>>(hs_pk, kw_pk, kb, k_pk, E_, E_, 0, 0, 24, BS_, 1.f);
    hgemm<0,2><<<gproj, 256, SMEMSZ>>>(hs_pk, vw_pk, vb, v_pk, E_, E_, 0, 0, 24, BS_, 1.f);

    // 2. scores = scale * Q K^T  (batched over B*H; M=N=576, K=64)
    dim3 gsc(S_ / 64, (S_ + 127) / 128, B_ * H_);
    hgemm<0,3><<<gsc, 256, SMEMSZ>>>(q_pk, k_pk, nullptr, attn, D_, D_,
                                     (long)S_ * D_, (long)S_ * D_, 2, S_, SCALE_);

    // 3. softmax in place
    softmax_kernel<<<B_ * H_ * S_, 128>>>(attn);

    // 4. PV -> ctx packed [B*S, E]  (M=576, N=64, K=576; B = v_pk [B,H,D,S])
    dim3 gpv(1, (S_ + 127) / 128, B_ * H_);
    hgemm<1,4><<<gpv, 256, SMEMSZ>>>(attn, v_pk, nullptr, ctx_pk, S_, S_,
                                     (long)S_ * S_, (long)D_ * S_, 18, S_, 1.f);

    // 5. output projection
    hgemm<0,0><<<gproj, 256, SMEMSZ>>>(ctx_pk, ow_pk, ob, out, E_, E_, 0, 0, 24, BS_, 1.f);
}

// round 4
// speedup vs baseline: 2.6866x; 1.1597x over previous
#include <cuda_runtime.h>
#include <cuda_bf16.h>
#include <math.h>
#include <stdint.h>

// ---------------- problem constants ----------------
constexpr int B_  = 32;
constexpr int S_  = 576;
constexpr int E_  = 768;
constexpr int H_  = 12;
constexpr int D_  = 64;
constexpr int BS_ = B_ * S_;                    // 18432
constexpr long OUT1  = (long)BS_ * E_;          // 14,155,776
constexpr long NATTN = (long)B_ * H_ * S_ * S_; // 127,401,984
constexpr float SCALE_ = 0.125f;

// ---------------- device scratch ----------------
__device__ unsigned g_hs_pk [BS_ * E_];
__device__ unsigned g_qw_pk [E_ * E_];
__device__ unsigned g_kw_pk [E_ * E_];
__device__ unsigned g_vw_pk [E_ * E_];
__device__ unsigned g_ow_pk [E_ * E_];
__device__ unsigned g_q_pk  [BS_ * E_];   // [B,H,S,D] packed (hi|lo<<16), pre-scaled by 0.125
__device__ unsigned g_k_pk  [BS_ * E_];   // [B,H,S,D]
__device__ unsigned g_v_pk  [BS_ * E_];   // [B,H,D,S]  (transposed)
__device__ unsigned g_ctx_pk[BS_ * E_];   // [B*S, E]
__device__ float    g_attn  [(size_t)NATTN];

// ---------------- helpers ----------------
__device__ __forceinline__ uint32_t smem_u32(const void* p) {
    uint32_t a;
    asm("{ .reg .u64 t; cvta.to.shared.u64 t, %1; cvt.u32.u64 %0, t; }" : "=r"(a) : "l"(p));
    return a;
}
__device__ __forceinline__ unsigned pack2u(__nv_bfloat16 a, __nv_bfloat16 b) {
    return (unsigned)__bfloat16_as_ushort(a) | ((unsigned)__bfloat16_as_ushort(b) << 16);
}
__device__ __forceinline__ unsigned packf(float x) {
    __nv_bfloat16 h = __float2bfloat16(x);
    __nv_bfloat16 l = __float2bfloat16(x - __bfloat162float(h));
    return pack2u(h, l);
}
__device__ __forceinline__ unsigned packhi2(float a, float b) {
    return pack2u(__float2bfloat16(a), __float2bfloat16(b));
}
__device__ __forceinline__ unsigned packlo2(float a, float b) {
    __nv_bfloat16 ha = __float2bfloat16(a), hb = __float2bfloat16(b);
    return pack2u(__float2bfloat16(a - __bfloat162float(ha)),
                  __float2bfloat16(b - __bfloat162float(hb)));
}
__device__ __forceinline__ void ldsm4(unsigned* r, uint32_t addr) {
    asm volatile("ldmatrix.sync.aligned.m8n8.x4.shared.b16 {%0,%1,%2,%3}, [%4];"
                 : "=r"(r[0]), "=r"(r[1]), "=r"(r[2]), "=r"(r[3]) : "r"(addr));
}
__device__ __forceinline__ void mma16816(float* d, const unsigned* a, const unsigned* b) {
    asm volatile(
        "mma.sync.aligned.m16n8k16.row.col.f32.bf16.bf16.f32 "
        "{%0,%1,%2,%3}, {%4,%5,%6,%7}, {%8,%9}, {%0,%1,%2,%3};"
        : "+f"(d[0]), "+f"(d[1]), "+f"(d[2]), "+f"(d[3])
        : "r"(a[0]), "r"(a[1]), "r"(a[2]), "r"(a[3]), "r"(b[0]), "r"(b[1]));
}

// ---------------- pack fp32 -> (bf16 hi | bf16 lo<<16) ----------------
__global__ void pack_split_kernel(const float* __restrict__ src,
                                  unsigned* __restrict__ dst, long n) {
    for (long i = (long)blockIdx.x * blockDim.x + threadIdx.x; i < n;
         i += (long)gridDim.x * blockDim.x)
        dst[i] = packf(src[i]);
}

// ============================================================================
// HMMA bf16-split GEMM (projections):  D = (A*B^T + bias) * scale
// Block 128x64, 8 warps (32x32), BK=32, double-buffered. 3 passes.
// MODE: 0 out fp32 [M,E]   1 packed -> [B,H,S,D]   2 packed -> [B,H,D,S]
// ============================================================================
constexpr int LDS_  = 40;
constexpr int A_H_  = 0;
constexpr int A_L_  = 128 * LDS_;
constexpr int B_H_  = 256 * LDS_;
constexpr int B_L_  = B_H_ + 64 * LDS_;
constexpr int STG_E = B_L_ + 64 * LDS_;
constexpr int STG_B = STG_E * 2;
constexpr int SMEMSZ = 2 * STG_B;

template<int MODE>
__global__ void __launch_bounds__(256)
hgemm(const unsigned* __restrict__ Aptr, const unsigned* __restrict__ Bptr,
      const float* __restrict__ bias, void* __restrict__ Cptr,
      int lda, int ldb, int NC, float scale)
{
    extern __shared__ char smem[];
    __nv_bfloat16* sm = (__nv_bfloat16*)smem;
    const uint32_t sbase = smem_u32(smem);

    const int tid = threadIdx.x, lane = tid & 31, wid = tid >> 5;
    const int warp_m = wid >> 1, warp_n = wid & 1;
    const int bm = blockIdx.y * 128, bn = blockIdx.x * 64;

    const int ar = tid >> 4;
    const int ac = (tid & 15) * 2;

    float acc[2][4][4];
    #pragma unroll
    for (int i = 0; i < 2; i++)
        #pragma unroll
        for (int j = 0; j < 4; j++)
            #pragma unroll
            for (int r = 0; r < 4; r++) acc[i][j][r] = 0.f;

    uint2 pa[8], pb[4];
    auto loadAB = [&](int k0) {
        #pragma unroll
        for (int i = 0; i < 8; i++)
            pa[i] = *(const uint2*)(Aptr + (long)(bm + ar + 16 * i) * lda + k0 + ac);
        #pragma unroll
        for (int i = 0; i < 4; i++)
            pb[i] = *(const uint2*)(Bptr + (long)(bn + ar + 16 * i) * ldb + k0 + ac);
    };
    auto stage = [&](int buf) {
        __nv_bfloat16* s = sm + buf * STG_E;
        #pragma unroll
        for (int i = 0; i < 8; i++) {
            const int off = (ar + 16 * i) * LDS_ + ac;
            *(unsigned*)(s + A_H_ + off) = __byte_perm(pa[i].x, pa[i].y, 0x5410);
            *(unsigned*)(s + A_L_ + off) = __byte_perm(pa[i].x, pa[i].y, 0x7632);
        }
        #pragma unroll
        for (int i = 0; i < 4; i++) {
            const int off = (ar + 16 * i) * LDS_ + ac;
            *(unsigned*)(s + B_H_ + off) = __byte_perm(pb[i].x, pb[i].y, 0x5410);
            *(unsigned*)(s + B_L_ + off) = __byte_perm(pb[i].x, pb[i].y, 0x7632);
        }
    };
    auto compute = [&](int buf) {
        const uint32_t base = sbase + buf * STG_B;
        #pragma unroll
        for (int ks = 0; ks < 2; ks++) {
            unsigned ah[2][4], al[2][4], bh[2][4], bl[2][4];
            #pragma unroll
            for (int mi = 0; mi < 2; mi++) {
                const uint32_t aoff =
                    ((warp_m * 32 + mi * 16 + (lane & 15)) * LDS_ + ks * 16 + ((lane >> 4) << 3)) * 2;
                ldsm4(ah[mi], base + A_H_ * 2 + aoff);
                ldsm4(al[mi], base + A_L_ * 2 + aoff);
            }
            #pragma unroll
            for (int np = 0; np < 2; np++) {
                const uint32_t boff =
                    ((warp_n * 32 + np * 16 + ((lane >> 4) & 1) * 8 + (lane & 7)) * LDS_
                     + ks * 16 + ((lane >> 3) & 1) * 8) * 2;
                ldsm4(bh[np], base + B_H_ * 2 + boff);
                ldsm4(bl[np], base + B_L_ * 2 + boff);
            }
            #pragma unroll
            for (int mi = 0; mi < 2; mi++)
                #pragma unroll
                for (int ni = 0; ni < 4; ni++) {
                    const unsigned* bhf = &bh[ni >> 1][(ni & 1) * 2];
                    const unsigned* blf = &bl[ni >> 1][(ni & 1) * 2];
                    mma16816(acc[mi][ni], ah[mi], bhf);
                    mma16816(acc[mi][ni], ah[mi], blf);
                    mma16816(acc[mi][ni], al[mi], bhf);
                }
        }
    };

    loadAB(0);
    for (int c = 0; c < NC; c++) {
        const int buf = c & 1;
        stage(buf);
        __syncthreads();
        if (c + 1 < NC) loadAB((c + 1) * 32);
        compute(buf);
        __syncthreads();
    }

    #pragma unroll
    for (int mi = 0; mi < 2; mi++)
        #pragma unroll
        for (int ni = 0; ni < 4; ni++) {
            const int gc = bn + warp_n * 32 + ni * 8 + (lane & 3) * 2;
            const float b0 = bias[gc], b1 = bias[gc + 1];
            #pragma unroll
            for (int r = 0; r < 2; r++) {
                const int gm = bm + warp_m * 32 + mi * 16 + (lane >> 2) + r * 8;
                const float v0 = (acc[mi][ni][r * 2 + 0] + b0) * scale;
                const float v1 = (acc[mi][ni][r * 2 + 1] + b1) * scale;
                if (MODE == 0) {
                    *(float2*)((float*)Cptr + (long)gm * E_ + gc) = make_float2(v0, v1);
                } else if (MODE == 1) {
                    const int b = gm / S_, s = gm % S_, h = gc >> 6, d = gc & 63;
                    *(uint2*)((unsigned*)Cptr + (((long)b * H_ + h) * S_ + s) * D_ + d)
                        = make_uint2(packf(v0), packf(v1));
                } else {
                    const int b = gm / S_, s = gm % S_, h = gc >> 6, d = gc & 63;
                    unsigned* dst = (unsigned*)Cptr + (((long)b * H_ + h) * D_ + d) * S_ + s;
                    dst[0]  = packf(v0);
                    dst[S_] = packf(v1);
                }
            }
        }
}

// ============================================================================
// Fused attention: scores (QK^T, pre-scaled Q) + softmax + attn write + PV.
// Block = 64 query rows of one (b,h). 8 warps: warp_m=wid>>1 (16 rows),
// warp_n=wid&1 (col half of each 64-col chunk / s half in PV).
// smem: Q(hi/lo) 18KB + KV double buffer 2x18KB = 54KB dynamic.
// ============================================================================
constexpr int LDSF   = 72;                      // bf16 elems per smem row
constexpr int OFF_QH = 0;
constexpr int OFF_QL = 64 * LDSF * 2;           // 9216
constexpr int OFF_KV = 2 * OFF_QL;              // 18432
constexpr int KVSTG  = 2 * 64 * LDSF * 2;       // 18432 per buffer (hi+lo)
constexpr int FSMEM  = OFF_KV + 2 * KVSTG;      // 55296

__global__ void __launch_bounds__(256, 1)
attn_fused(const unsigned* __restrict__ q_pk, const unsigned* __restrict__ k_pk,
           const unsigned* __restrict__ v_pk, float* __restrict__ attn,
           unsigned* __restrict__ ctx)
{
    extern __shared__ char smem[];
    const uint32_t sbase = smem_u32(smem);
    __shared__ float s_mx[2][64], s_sm[2][64];

    const int tid = threadIdx.x, lane = tid & 31, wid = tid >> 5;
    const int warp_m = wid >> 1, warp_n = wid & 1;
    const int bm = blockIdx.x * 64;
    const int z  = blockIdx.y;                 // b*H + h

    const unsigned* qorg = q_pk + ((long)z * S_ + bm) * D_;
    const unsigned* korg = k_pk + (long)z * S_ * D_;
    const unsigned* vorg = v_pk + (long)z * D_ * S_;
    float* attnz = attn + (long)z * S_ * S_;

    uint2 tr[8];
    auto load_tile = [&](const unsigned* org, int rstride) {
        #pragma unroll
        for (int i = 0; i < 8; i++) {
            const int p = tid + i * 256;
            tr[i] = *(const uint2*)(org + (long)(p >> 5) * rstride + (p & 31) * 2);
        }
    };
    auto stage_tile = [&](int byteoff) {
        char* dH = smem + byteoff;
        char* dL = smem + byteoff + 64 * LDSF * 2;
        #pragma unroll
        for (int i = 0; i < 8; i++) {
            const int p = tid + i * 256;
            const int off = ((p >> 5) * LDSF + (p & 31) * 2) * 2;
            *(unsigned*)(dH + off) = __byte_perm(tr[i].x, tr[i].y, 0x5410);
            *(unsigned*)(dL + off) = __byte_perm(tr[i].x, tr[i].y, 0x7632);
        }
    };

    // ---- stage Q, preload Q fragments (kept in regs for all 9 chunks) ----
    load_tile(qorg, D_);
    stage_tile(OFF_QH);
    __syncthreads();
    unsigned qh[4][4], ql[4][4];
    #pragma unroll
    for (int ks = 0; ks < 4; ks++) {
        const uint32_t aoff =
            ((warp_m * 16 + (lane & 15)) * LDSF + ks * 16 + ((lane >> 4) << 3)) * 2;
        ldsm4(qh[ks], sbase + OFF_QH + aoff);
        ldsm4(ql[ks], sbase + OFF_QL + aoff);
    }

    // ---- phase 1: S = Q K^T (scale pre-folded into Q) ----
    float sf[9][4][4];
    #pragma unroll
    for (int c = 0; c < 9; c++)
        #pragma unroll
        for (int f = 0; f < 4; f++)
            #pragma unroll
            for (int r = 0; r < 4; r++) sf[c][f][r] = 0.f;

    load_tile(korg, D_);   // chunk 0
    #pragma unroll
    for (int c = 0; c < 9; c++) {
        const int buf = c & 1;
        stage_tile(OFF_KV + buf * KVSTG);
        __syncthreads();
        if (c < 8) load_tile(korg + (long)(c + 1) * 64 * D_, D_);
        const uint32_t baseH = sbase + OFF_KV + buf * KVSTG;
        const uint32_t baseL = baseH + 64 * LDSF * 2;
        #pragma unroll
        for (int ks = 0; ks < 4; ks++) {
            unsigned kh[2][4], kl[2][4];
            #pragma unroll
            for (int np = 0; np < 2; np++) {
                const uint32_t boff =
                    ((warp_n * 32 + np * 16 + ((lane >> 4) & 1) * 8 + (lane & 7)) * LDSF
                     + ks * 16 + ((lane >> 3) & 1) * 8) * 2;
                ldsm4(kh[np], baseH + boff);
                ldsm4(kl[np], baseL + boff);
            }
            #pragma unroll
            for (int f = 0; f < 4; f++) {
                const unsigned* BH = &kh[f >> 1][(f & 1) * 2];
                const unsigned* BL = &kl[f >> 1][(f & 1) * 2];
                mma16816(sf[c][f], qh[ks], BH);
                mma16816(sf[c][f], qh[ks], BL);
                mma16816(sf[c][f], ql[ks], BH);
            }
        }
        __syncthreads();
    }

    // prefetch V chunk 0 (hides latency under softmax)
    load_tile(vorg, S_);

    // ---- phase 2: softmax over full rows ----
    const int r1 = warp_m * 16 + (lane >> 2), r2 = r1 + 8;
    float m1 = -INFINITY, m2 = -INFINITY;
    #pragma unroll
    for (int c = 0; c < 9; c++)
        #pragma unroll
        for (int f = 0; f < 4; f++) {
            m1 = fmaxf(m1, fmaxf(sf[c][f][0], sf[c][f][1]));
            m2 = fmaxf(m2, fmaxf(sf[c][f][2], sf[c][f][3]));
        }
    #pragma unroll
    for (int o = 1; o <= 2; o <<= 1) {
        m1 = fmaxf(m1, __shfl_xor_sync(0xffffffffu, m1, o));
        m2 = fmaxf(m2, __shfl_xor_sync(0xffffffffu, m2, o));
    }
    if ((lane & 3) == 0) { s_mx[warp_n][r1] = m1; s_mx[warp_n][r2] = m2; }
    __syncthreads();
    m1 = fmaxf(s_mx[0][r1], s_mx[1][r1]);
    m2 = fmaxf(s_mx[0][r2], s_mx[1][r2]);

    float s1 = 0.f, s2 = 0.f;
    #pragma unroll
    for (int c = 0; c < 9; c++)
        #pragma unroll
        for (int f = 0; f < 4; f++) {
            sf[c][f][0] = __expf(sf[c][f][0] - m1);
            sf[c][f][1] = __expf(sf[c][f][1] - m1);
            sf[c][f][2] = __expf(sf[c][f][2] - m2);
            sf[c][f][3] = __expf(sf[c][f][3] - m2);
            s1 += sf[c][f][0] + sf[c][f][1];
            s2 += sf[c][f][2] + sf[c][f][3];
        }
    #pragma unroll
    for (int o = 1; o <= 2; o <<= 1) {
        s1 += __shfl_xor_sync(0xffffffffu, s1, o);
        s2 += __shfl_xor_sync(0xffffffffu, s2, o);
    }
    if ((lane & 3) == 0) { s_sm[warp_n][r1] = s1; s_sm[warp_n][r2] = s2; }
    __syncthreads();
    const float inv1 = 1.f / (s_sm[0][r1] + s_sm[1][r1]);
    const float inv2 = 1.f / (s_sm[0][r2] + s_sm[1][r2]);

    // ---- phase 3: normalize + write attn (fp32, 32B-sector aligned) ----
    #pragma unroll
    for (int c = 0; c < 9; c++)
        #pragma unroll
        for (int f = 0; f < 4; f++) {
            sf[c][f][0] *= inv1; sf[c][f][1] *= inv1;
            sf[c][f][2] *= inv2; sf[c][f][3] *= inv2;
            const int col = c * 64 + warp_n * 32 + f * 8 + (lane & 3) * 2;
            *(float2*)(attnz + (long)(bm + r1) * S_ + col) = make_float2(sf[c][f][0], sf[c][f][1]);
            *(float2*)(attnz + (long)(bm + r2) * S_ + col) = make_float2(sf[c][f][2], sf[c][f][3]);
        }

    // ---- phase 4: PV. P frags from regs (bf16 hi/lo), V streamed hi/lo. ----
    float dacc[8][4];
    #pragma unroll
    for (int f = 0; f < 8; f++)
        #pragma unroll
        for (int r = 0; r < 4; r++) dacc[f][r] = 0.f;

    #pragma unroll
    for (int c = 0; c < 9; c++) {
        const int buf = c & 1;
        stage_tile(OFF_KV + buf * KVSTG);
        __syncthreads();
        if (c < 8) load_tile(vorg + (long)(c + 1) * 64, S_);
        const uint32_t baseH = sbase + OFF_KV + buf * KVSTG;
        const uint32_t baseL = baseH + 64 * LDSF * 2;
        #pragma unroll
        for (int g = 0; g < 2; g++) {
            // P A-frags for this k16 group (cols warp_n*32 + g*16 .. +15)
            unsigned ph[4], pl[4];
            {
                const float* f0 = sf[c][g * 2];
                const float* f1 = sf[c][g * 2 + 1];
                ph[0] = packhi2(f0[0], f0[1]); ph[1] = packhi2(f0[2], f0[3]);
                ph[2] = packhi2(f1[0], f1[1]); ph[3] = packhi2(f1[2], f1[3]);
                pl[0] = packlo2(f0[0], f0[1]); pl[1] = packlo2(f0[2], f0[3]);
                pl[2] = packlo2(f1[0], f1[1]); pl[3] = packlo2(f1[2], f1[3]);
            }
            const int ksv = warp_n * 2 + g;   // k16 index within the 64-s tile
            unsigned vh[4][4], vl[4][4];
            #pragma unroll
            for (int np = 0; np < 4; np++) {
                const uint32_t boff =
                    ((np * 16 + ((lane >> 4) & 1) * 8 + (lane & 7)) * LDSF
                     + ksv * 16 + ((lane >> 3) & 1) * 8) * 2;
                ldsm4(vh[np], baseH + boff);
                ldsm4(vl[np], baseL + boff);
            }
            #pragma unroll
            for (int f = 0; f < 8; f++) {
                const unsigned* BH = &vh[f >> 1][(f & 1) * 2];
                const unsigned* BL = &vl[f >> 1][(f & 1) * 2];
                mma16816(dacc[f], ph, BH);
                mma16816(dacc[f], ph, BL);
                mma16816(dacc[f], pl, BH);
            }
        }
        __syncthreads();
    }

    // ---- phase 5: cross-warp_n reduction + ctx write ----
    float* sred = (float*)smem;   // [64][68] fp32, reuses Q area (dead)
    if (warp_n == 0) {
        #pragma unroll
        for (int f = 0; f < 8; f++)
            #pragma unroll
            for (int rr = 0; rr < 2; rr++) {
                const int row = warp_m * 16 + (lane >> 2) + rr * 8;
                const int col = f * 8 + (lane & 3) * 2;
                sred[row * 68 + col]     = dacc[f][rr * 2];
                sred[row * 68 + col + 1] = dacc[f][rr * 2 + 1];
            }
    }
    __syncthreads();
    if (warp_n == 1) {
        const int b = z / H_, h = z % H_;
        #pragma unroll
        for (int f = 0; f < 8; f++)
            #pragma unroll
            for (int rr = 0; rr < 2; rr++) {
                const int row = warp_m * 16 + (lane >> 2) + rr * 8;
                const int col = f * 8 + (lane & 3) * 2;
                const float v0 = dacc[f][rr * 2]     + sred[row * 68 + col];
                const float v1 = dacc[f][rr * 2 + 1] + sred[row * 68 + col + 1];
                *(uint2*)(ctx + ((long)(b * S_ + bm + row)) * E_ + h * D_ + col)
                    = make_uint2(packf(v0), packf(v1));
            }
    }
}

// ============================================================================
// Launch
// ============================================================================
extern "C" void kernel_launch(void* const* d_in, const int* in_sizes, int n_in,
                              void* d_out, int out_size)
{
    const float* hs = (const float*)d_in[0];
    const float* qw = (const float*)d_in[1];
    const float* qb = (const float*)d_in[2];
    const float* kw = (const float*)d_in[3];
    const float* kb = (const float*)d_in[4];
    const float* vw = (const float*)d_in[5];
    const float* vb = (const float*)d_in[6];
    const float* ow = (const float*)d_in[7];
    const float* ob = (const float*)d_in[8];
    float* out = (float*)d_out;

    unsigned *hs_pk, *qw_pk, *kw_pk, *vw_pk, *ow_pk, *q_pk, *k_pk, *v_pk, *ctx_pk;
    float* attn_fb;
    cudaGetSymbolAddress((void**)&hs_pk, g_hs_pk);
    cudaGetSymbolAddress((void**)&qw_pk, g_qw_pk);
    cudaGetSymbolAddress((void**)&kw_pk, g_kw_pk);
    cudaGetSymbolAddress((void**)&vw_pk, g_vw_pk);
    cudaGetSymbolAddress((void**)&ow_pk, g_ow_pk);
    cudaGetSymbolAddress((void**)&q_pk,  g_q_pk);
    cudaGetSymbolAddress((void**)&k_pk,  g_k_pk);
    cudaGetSymbolAddress((void**)&v_pk,  g_v_pk);
    cudaGetSymbolAddress((void**)&ctx_pk, g_ctx_pk);
    cudaGetSymbolAddress((void**)&attn_fb, g_attn);
    float* attn = ((long)out_size >= OUT1 + NATTN) ? (out + OUT1) : attn_fb;

    cudaFuncSetAttribute(hgemm<0>, cudaFuncAttributeMaxDynamicSharedMemorySize, SMEMSZ);
    cudaFuncSetAttribute(hgemm<1>, cudaFuncAttributeMaxDynamicSharedMemorySize, SMEMSZ);
    cudaFuncSetAttribute(hgemm<2>, cudaFuncAttributeMaxDynamicSharedMemorySize, SMEMSZ);
    cudaFuncSetAttribute(attn_fused, cudaFuncAttributeMaxDynamicSharedMemorySize, FSMEM);

    // 0. pack inputs
    pack_split_kernel<<<2048, 256>>>(hs, hs_pk, (long)BS_ * E_);
    pack_split_kernel<<<512, 256>>>(qw, qw_pk, (long)E_ * E_);
    pack_split_kernel<<<512, 256>>>(kw, kw_pk, (long)E_ * E_);
    pack_split_kernel<<<512, 256>>>(vw, vw_pk, (long)E_ * E_);
    pack_split_kernel<<<512, 256>>>(ow, ow_pk, (long)E_ * E_);

    // 1. QKV projections (Q pre-scaled by 0.125 — exact, power of 2)
    dim3 gproj(E_ / 64, BS_ / 128, 1);
    hgemm<1><<<gproj, 256, SMEMSZ>>>(hs_pk, qw_pk, qb, q_pk, E_, E_, 24, SCALE_);
    hgemm<1><<<gproj, 256, SMEMSZ>>>(hs_pk, kw_pk, kb, k_pk, E_, E_, 24, 1.f);
    hgemm<2><<<gproj, 256, SMEMSZ>>>(hs_pk, vw_pk, vb, v_pk, E_, E_, 24, 1.f);

    // 2. fused scores + softmax + attn write + PV
    dim3 gf(S_ / 64, B_ * H_, 1);
    attn_fused<<<gf, 256, FSMEM>>>(q_pk, k_pk, v_pk, attn, ctx_pk);

    // 3. output projection
    hgemm<0><<<gproj, 256, SMEMSZ>>>(ctx_pk, ow_pk, ob, out, E_, E_, 24, 1.f);
}